// round 16
// baseline (speedup 1.0000x reference)
#include <cuda_runtime.h>
#include <cuda_fp16.h>
#include <math.h>

#define B_   16
#define L_   1024
#define IN_  32
#define D_   256
#define H_   8
#define NL_  2
#define DFF_ 1024
#define DH_  32
#define BL_  (B_*L_)

// ---------------- half-operand weight layout ----------------
#define OFF_INW  0
#define SZ_INW   (D_*IN_)
#define OFF_QKVW (OFF_INW+SZ_INW)
#define SZ_QKVW  (NL_*3*D_*D_)
#define OFF_OUTW (OFF_QKVW+SZ_QKVW)
#define SZ_OUTW  (NL_*D_*D_)
#define OFF_FF1W (OFF_OUTW+SZ_OUTW)
#define SZ_FF1W  (NL_*DFF_*D_)
#define OFF_FF2W (OFF_FF1W+SZ_FF1W)
#define SZ_FF2W  (NL_*D_*DFF_)
#define WR_TOTAL (OFF_FF2W+SZ_FF2W)

// ---------------- scratch (device globals; zero-initialized) ----------------
__device__ float g_x[BL_*D_];         // exact activations (residual / outputs)
__device__ __half g_xr[BL_*D_];       // half copy (MMA A operand)
__device__ __half g_qkvh[BL_*3*D_];   // Q|K|V half [BL][768]
__device__ __half g_o[BL_*D_];        // attention out (half)
__device__ __half g_h[BL_*DFF_];      // ff hidden half
__device__ float g_t[BL_];
__device__ unsigned char g_mask[BL_];
__device__ int g_len[B_];
__device__ __half g_wh[WR_TOTAL];     // half weights
__device__ __half g_fr[BL_*IN_];      // half features

// ---------------- helpers ----------------
__device__ __forceinline__ void mma_f16(float* d, const unsigned* a,
                                        const unsigned* b, const float* c) {
  asm volatile(
    "mma.sync.aligned.m16n8k16.row.col.f32.f16.f16.f32 "
    "{%0,%1,%2,%3},{%4,%5,%6,%7},{%8,%9},{%10,%11,%12,%13};"
    : "=f"(d[0]),"=f"(d[1]),"=f"(d[2]),"=f"(d[3])
    : "r"(a[0]),"r"(a[1]),"r"(a[2]),"r"(a[3]),
      "r"(b[0]),"r"(b[1]),
      "f"(c[0]),"f"(c[1]),"f"(c[2]),"f"(c[3]));
}
__device__ __forceinline__ void ldm4(unsigned* r, unsigned saddr) {
  asm volatile("ldmatrix.sync.aligned.m8n8.x4.shared.b16 {%0,%1,%2,%3}, [%4];"
    : "=r"(r[0]),"=r"(r[1]),"=r"(r[2]),"=r"(r[3]) : "r"(saddr));
}
__device__ __forceinline__ void ldm4t(unsigned* r, unsigned saddr) {
  asm volatile("ldmatrix.sync.aligned.m8n8.x4.trans.shared.b16 {%0,%1,%2,%3}, [%4];"
    : "=r"(r[0]),"=r"(r[1]),"=r"(r[2]),"=r"(r[3]) : "r"(saddr));
}
__device__ __forceinline__ void cp16(unsigned* smem_ptr, const void* gptr) {
  unsigned s = (unsigned)__cvta_generic_to_shared(smem_ptr);
  asm volatile("cp.async.ca.shared.global [%0], [%1], 16;" :: "r"(s), "l"(gptr));
}
#define CP_COMMIT asm volatile("cp.async.commit_group;")
#define CP_WAIT1  asm volatile("cp.async.wait_group 1;")
#define CP_WAIT0  asm volatile("cp.async.wait_group 0;")
__device__ __forceinline__ float lg2f(float x) {
  float r; asm("lg2.approx.f32 %0, %1;" : "=f"(r) : "f"(x)); return r;
}
__device__ __forceinline__ float ex2f(float x) {
  float r; asm("ex2.approx.f32 %0, %1;" : "=f"(r) : "f"(x)); return r;
}
__device__ __forceinline__ unsigned h2u(half2 h) {
  return *reinterpret_cast<unsigned*>(&h);
}

// ---------------- weight/feature conversion to half ----------------
__global__ __launch_bounds__(256) void wconv_kernel(
    const float* __restrict__ feat, const float* __restrict__ in_w,
    const float* __restrict__ qkv_w, const float* __restrict__ out_w,
    const float* __restrict__ ff1_w, const float* __restrict__ ff2_w) {
  int g = blockIdx.x*blockDim.x + threadIdx.x;
  int stride = gridDim.x*blockDim.x;
  for (int i = g; i < BL_*IN_; i += stride) g_fr[i] = __float2half_rn(feat[i]);
  for (int i = g; i < SZ_INW;  i += stride) g_wh[OFF_INW+i]  = __float2half_rn(in_w[i]);
  for (int i = g; i < SZ_QKVW; i += stride) g_wh[OFF_QKVW+i] = __float2half_rn(qkv_w[i]);
  for (int i = g; i < SZ_OUTW; i += stride) g_wh[OFF_OUTW+i] = __float2half_rn(out_w[i]);
  for (int i = g; i < SZ_FF1W; i += stride) g_wh[OFF_FF1W+i] = __float2half_rn(ff1_w[i]);
  for (int i = g; i < SZ_FF2W; i += stride) g_wh[OFF_FF2W+i] = __float2half_rn(ff2_w[i]);
}

// ---------------- fused prep ----------------
__global__ __launch_bounds__(1024) void prep_kernel(
    const unsigned int* __restrict__ mraw, const float* __restrict__ feat) {
  __shared__ int bad;
  __shared__ int slen;
  __shared__ float wsum[32];
  int b = blockIdx.x, tid = threadIdx.x;
  int lane = tid & 31, warp = tid >> 5;
  if (tid == 0) { bad = 0; slen = 0; }
  __syncthreads();
  for (int k = tid; k < 4096; k += 1024) {
    unsigned v = mraw[k];
    if (v != 0u && v != 1u && v != 0x3F800000u) atomicOr(&bad, 1);
  }
  __syncthreads();
  int mode4 = !bad;
  int j = b*L_ + tid;
  unsigned char m = mode4 ? (mraw[j] != 0u)
                          : (((const unsigned char*)mraw)[j] != 0);
  g_mask[j] = m;
  if (!m) atomicAdd(&slen, 1);
  float v = feat[(long)j*IN_ + (IN_-2)];
#pragma unroll
  for (int off = 1; off < 32; off <<= 1) {
    float n = __shfl_up_sync(~0u, v, off);
    if (lane >= off) v += n;
  }
  if (lane == 31) wsum[warp] = v;
  __syncthreads();
  if (warp == 0) {
    float w = wsum[lane];
#pragma unroll
    for (int off = 1; off < 32; off <<= 1) {
      float n = __shfl_up_sync(~0u, w, off);
      if (lane >= off) w += n;
    }
    wsum[lane] = w;
  }
  __syncthreads();
  float base = warp ? wsum[warp-1] : 0.f;
  g_t[j] = v + base;
  if (tid == 0) g_len[b] = slen;
}

// ---------------- FP16 GEMM (2-stage, ldmatrix) — embed/QKV/FF1 -----------
// WMODE: 1 = Ch half; 2 = Cf fp32 + Ch half
#define GEMM_SMEM (7680*4)
template<int WMODE, bool RELU, bool PE>
__global__ __launch_bounds__(256, 3) void gemm_tc(
    const __half* __restrict__ A, const __half* __restrict__ W,
    const float* __restrict__ bias, float* __restrict__ Cf,
    __half* __restrict__ Ch, const float* __restrict__ pe, int N, int K) {
  int m_blk = blockIdx.y * 128, n_blk = blockIdx.x * 64;
  if ((m_blk & (L_-1)) >= g_len[m_blk >> 10]) return;
  extern __shared__ unsigned gsm[];
  unsigned sbase = (unsigned)__cvta_generic_to_shared(gsm);
  int tid = threadIdx.x, lane = tid & 31, warp = tid >> 5;
  int wm = warp >> 1, wn = warp & 1;
  int gr = lane >> 2, q = lane & 3;
  int l15 = lane & 15, lhi = (lane >> 4) << 2;
  float acc[2][4][4] = {};

  auto ld_stage = [&](int s, int k0) {
    unsigned* As = gsm + s*2560;
#pragma unroll
    for (int p = 0; p < 2; p++) {
      int id = p*256 + tid, row = id >> 2, c4 = id & 3;
      cp16(As + row*20 + c4*4, A + (long)(m_blk + row)*K + k0 + c4*8);
    }
    unsigned* Bs = gsm + 5120 + s*1280;
    {
      int row = tid >> 2, c4 = tid & 3;
      cp16(Bs + row*20 + c4*4, W + (long)(n_blk + row)*K + k0 + c4*8);
    }
  };

  ld_stage(0, 0); CP_COMMIT;
  int st = 0;
  for (int k0 = 0; k0 < K; k0 += 32) {
    if (k0 + 32 < K) { ld_stage(st^1, k0+32); CP_COMMIT; CP_WAIT1; }
    else CP_WAIT0;
    __syncthreads();
#pragma unroll
    for (int kk = 0; kk < 2; kk++) {
      unsigned coff = kk*8 + lhi;
      unsigned afr[2][4];
#pragma unroll
      for (int mt = 0; mt < 2; mt++)
        ldm4(afr[mt], sbase + ((st*2560 + (wm*32 + mt*16 + l15)*20 + coff) << 2));
      unsigned bfr[4][2];
#pragma unroll
      for (int p2 = 0; p2 < 2; p2++) {
        unsigned t[4];
        ldm4(t, sbase + ((5120 + st*1280 + (wn*32 + p2*16 + l15)*20 + coff) << 2));
        bfr[p2*2][0]=t[0];   bfr[p2*2][1]=t[2];
        bfr[p2*2+1][0]=t[1]; bfr[p2*2+1][1]=t[3];
      }
#pragma unroll
      for (int mt = 0; mt < 2; mt++)
#pragma unroll
        for (int nt = 0; nt < 4; nt++)
          mma_f16(acc[mt][nt], afr[mt], bfr[nt], acc[mt][nt]);
    }
    __syncthreads();
    st ^= 1;
  }
#pragma unroll
  for (int mt = 0; mt < 2; mt++) {
    int r0 = m_blk + wm*32 + mt*16 + gr;
#pragma unroll
    for (int nt = 0; nt < 4; nt++) {
      int c0 = n_blk + wn*32 + nt*8 + 2*q;
      float b0v = bias[c0], b1v = bias[c0+1];
      float v0 = acc[mt][nt][0] + b0v, v1 = acc[mt][nt][1] + b1v;
      float v2 = acc[mt][nt][2] + b0v, v3 = acc[mt][nt][3] + b1v;
      if (PE) {
        v0 += pe[(long)(r0 & (L_-1))*D_ + c0];
        v1 += pe[(long)(r0 & (L_-1))*D_ + c0 + 1];
        v2 += pe[(long)((r0+8) & (L_-1))*D_ + c0];
        v3 += pe[(long)((r0+8) & (L_-1))*D_ + c0 + 1];
      }
      if (RELU) { v0=fmaxf(v0,0.f); v1=fmaxf(v1,0.f); v2=fmaxf(v2,0.f); v3=fmaxf(v3,0.f); }
      if (WMODE == 2) {
        *(float2*)(Cf + (long)r0*N + c0)     = make_float2(v0, v1);
        *(float2*)(Cf + (long)(r0+8)*N + c0) = make_float2(v2, v3);
      }
      *(half2*)(Ch + (long)r0*N + c0)     = __floats2half2_rn(v0, v1);
      *(half2*)(Ch + (long)(r0+8)*N + c0) = __floats2half2_rn(v2, v3);
    }
  }
}

// ---------------- fused GEMM + residual + LayerNorm (N = 256 = full row) ---
// x_new = LN(g_x + A@W^T + bias) * gamma + beta  -> g_x (fp32) + g_xr (half)
// BM=64, BN=256, BK=32; 8 warps (2m x 4n), warp tile 32x64.
// smem words: A 2x(64*20=1280) @0, B 2x(256*20=5120) @2560. total 12800 w.
#define GLN_SMEM (12800*4)
__global__ __launch_bounds__(256, 2) void gemm_ln(
    const __half* __restrict__ A, const __half* __restrict__ W,
    const float* __restrict__ bias,
    const float* __restrict__ gam, const float* __restrict__ bet, int K) {
  int m_blk = blockIdx.x * 64;
  int len = g_len[m_blk >> 10];
  if ((m_blk & (L_-1)) >= len) return;
  extern __shared__ unsigned gsm[];
  unsigned sbase = (unsigned)__cvta_generic_to_shared(gsm);
  int tid = threadIdx.x, lane = tid & 31, warp = tid >> 5;
  int wm = warp >> 2, wn = warp & 3;
  int gr = lane >> 2, q = lane & 3;
  int l15 = lane & 15, lhi = (lane >> 4) << 2;
  float acc[2][8][4] = {};

  auto ld_stage = [&](int s, int k0) {
    unsigned* As = gsm + s*1280;
    {
      int row = tid >> 2, c4 = tid & 3;
      cp16(As + row*20 + c4*4, A + (long)(m_blk + row)*K + k0 + c4*8);
    }
    unsigned* Bs = gsm + 2560 + s*5120;
#pragma unroll
    for (int p = 0; p < 4; p++) {
      int id = p*256 + tid, row = id >> 2, c4 = id & 3;
      cp16(Bs + row*20 + c4*4, W + (long)row*K + k0 + c4*8);
    }
  };

  ld_stage(0, 0); CP_COMMIT;
  int st = 0;
  for (int k0 = 0; k0 < K; k0 += 32) {
    if (k0 + 32 < K) { ld_stage(st^1, k0+32); CP_COMMIT; CP_WAIT1; }
    else CP_WAIT0;
    __syncthreads();
#pragma unroll
    for (int kk = 0; kk < 2; kk++) {
      unsigned coff = kk*8 + lhi;
      unsigned afr[2][4];
#pragma unroll
      for (int mt = 0; mt < 2; mt++)
        ldm4(afr[mt], sbase + ((st*1280 + (wm*32 + mt*16 + l15)*20 + coff) << 2));
      unsigned bfr[8][2];
#pragma unroll
      for (int p2 = 0; p2 < 4; p2++) {
        unsigned t[4];
        ldm4(t, sbase + ((2560 + st*5120 + (wn*64 + p2*16 + l15)*20 + coff) << 2));
        bfr[p2*2][0]=t[0];   bfr[p2*2][1]=t[2];
        bfr[p2*2+1][0]=t[1]; bfr[p2*2+1][1]=t[3];
      }
#pragma unroll
      for (int mt = 0; mt < 2; mt++)
#pragma unroll
        for (int nt = 0; nt < 8; nt++)
          mma_f16(acc[mt][nt], afr[mt], bfr[nt], acc[mt][nt]);
    }
    __syncthreads();
    st ^= 1;
  }
  __syncthreads();   // smem now reused for LN reduction

  // add bias + residual (g_x)
#pragma unroll
  for (int mt = 0; mt < 2; mt++) {
    int r0 = m_blk + wm*32 + mt*16 + gr;
#pragma unroll
    for (int nt = 0; nt < 8; nt++) {
      int c0 = wn*64 + nt*8 + 2*q;
      float2 bv = *(const float2*)(bias + c0);
      float2 x0 = *(const float2*)(g_x + (long)r0*D_ + c0);
      float2 x1 = *(const float2*)(g_x + (long)(r0+8)*D_ + c0);
      acc[mt][nt][0] += bv.x + x0.x; acc[mt][nt][1] += bv.y + x0.y;
      acc[mt][nt][2] += bv.x + x1.x; acc[mt][nt][3] += bv.y + x1.y;
    }
  }
  // per-row sum and sumsq, reduced across quad lanes then across 4 n-warps
  float* sred = (float*)gsm;   // [0:256) sums, [256:512) sumsqs (wn*64+row)
#pragma unroll
  for (int mt = 0; mt < 2; mt++) {
    float s0=0.f, s1=0.f, t0=0.f, t1=0.f;
#pragma unroll
    for (int nt = 0; nt < 8; nt++) {
      float a0=acc[mt][nt][0], a1=acc[mt][nt][1];
      float a2=acc[mt][nt][2], a3=acc[mt][nt][3];
      s0 += a0 + a1; t0 += a0*a0 + a1*a1;
      s1 += a2 + a3; t1 += a2*a2 + a3*a3;
    }
    s0 += __shfl_xor_sync(~0u, s0, 1); s0 += __shfl_xor_sync(~0u, s0, 2);
    s1 += __shfl_xor_sync(~0u, s1, 1); s1 += __shfl_xor_sync(~0u, s1, 2);
    t0 += __shfl_xor_sync(~0u, t0, 1); t0 += __shfl_xor_sync(~0u, t0, 2);
    t1 += __shfl_xor_sync(~0u, t1, 1); t1 += __shfl_xor_sync(~0u, t1, 2);
    if (q == 0) {
      int lr = wm*32 + mt*16 + gr;
      sred[wn*64 + lr]       = s0;  sred[256 + wn*64 + lr]     = t0;
      sred[wn*64 + lr + 8]   = s1;  sred[256 + wn*64 + lr + 8] = t1;
    }
  }
  __syncthreads();
#pragma unroll
  for (int mt = 0; mt < 2; mt++) {
    int lr = wm*32 + mt*16 + gr;
    float su0 = sred[lr] + sred[64+lr] + sred[128+lr] + sred[192+lr];
    float su1 = sred[lr+8] + sred[64+lr+8] + sred[128+lr+8] + sred[192+lr+8];
    float sq0 = sred[256+lr] + sred[256+64+lr] + sred[256+128+lr] + sred[256+192+lr];
    float sq1 = sred[256+lr+8] + sred[256+64+lr+8] + sred[256+128+lr+8] + sred[256+192+lr+8];
    float m0 = su0 * (1.f/D_), m1 = su1 * (1.f/D_);
    float rstd0 = rsqrtf(sq0*(1.f/D_) - m0*m0 + 1e-5f);
    float rstd1 = rsqrtf(sq1*(1.f/D_) - m1*m1 + 1e-5f);
    int r0 = m_blk + wm*32 + mt*16 + gr;
    bool v0 = (r0 & (L_-1)) < len, v1 = ((r0+8) & (L_-1)) < len;
#pragma unroll
    for (int nt = 0; nt < 8; nt++) {
      int c0 = wn*64 + nt*8 + 2*q;
      float2 gv = *(const float2*)(gam + c0);
      float2 bv = *(const float2*)(bet + c0);
      float o0 = (acc[mt][nt][0]-m0)*rstd0*gv.x + bv.x;
      float o1 = (acc[mt][nt][1]-m0)*rstd0*gv.y + bv.y;
      float o2 = (acc[mt][nt][2]-m1)*rstd1*gv.x + bv.x;
      float o3 = (acc[mt][nt][3]-m1)*rstd1*gv.y + bv.y;
      if (v0) {
        *(float2*)(g_x + (long)r0*D_ + c0) = make_float2(o0, o1);
        *(half2*)(g_xr + (long)r0*D_ + c0) = __floats2half2_rn(o0, o1);
      }
      if (v1) {
        *(float2*)(g_x + (long)(r0+8)*D_ + c0) = make_float2(o2, o3);
        *(half2*)(g_xr + (long)(r0+8)*D_ + c0) = __floats2half2_rn(o2, o3);
      }
    }
  }
}

// ---------------- flash attention: no-max softmax (round-15 version) ------
#define ATT_SMEM (10016*4)
#define N_WORK   (B_*H_*(L_/128))
__global__ __launch_bounds__(128, 3) void attn_mma(
    const float* __restrict__ tw_p, const float* __restrict__ tb_p) {
  extern __shared__ unsigned smem[];
  unsigned* Pb = smem;
  unsigned sbase = (unsigned)__cvta_generic_to_shared(smem);
  float* tq = (float*)(smem + 9728);

  int tid = threadIdx.x, lane = tid & 31, warp = tid >> 5;
  int gr = lane >> 2, q = lane & 3;
  int l15 = lane & 15, lhi = (lane >> 4) << 2;

  const float LOG2E = 1.4426950408889634f;
  float tw = -fabsf(tw_p[0]);
  float tbL = tb_p[0] * LOG2E;
  const float scaleL = 0.17677669529663687f * LOG2E;

  for (int w = blockIdx.x; w < N_WORK; w += gridDim.x) {
    int iblk = w & 7, bh = w >> 3;
    int b = bh >> 3, h = bh & 7;
    int i0 = iblk * 128;
    int len = g_len[b];
    if (i0 >= len) continue;
    int njt = (len + 63) >> 6;

    auto ld_kv = [&](int s, int j0) {
      unsigned* Kb = smem + 4608 + s*1280;
      unsigned* Vb = smem + 7168 + s*1280;
#pragma unroll
      for (int p = 0; p < 2; p++) {
        int id = p*128 + tid, row = id >> 2, c4 = id & 3;
        long base = (long)(b*L_ + j0 + row)*768 + h*DH_ + c4*8;
        cp16(Kb + row*20 + c4*4, g_qkvh + base + 256);
        cp16(Vb + row*20 + c4*4, g_qkvh + base + 512);
      }
      if (tid < 16)      cp16(smem + 9856 + s*64 + tid*4, g_t + b*L_ + j0 + tid*4);
      else if (tid < 20) cp16(smem + 9984 + s*16 + (tid-16)*4,
                              g_mask + b*L_ + j0 + (tid-16)*16);
    };

#pragma unroll
    for (int p = 0; p < 4; p++) {
      int id = p*128 + tid, row = id >> 2, c4 = id & 3;
      cp16(Pb + row*36 + c4*4,
           g_qkvh + (long)(b*L_ + i0 + row)*768 + h*DH_ + c4*8);
    }
    if (tid < 32) cp16((unsigned*)tq + tid*4, g_t + b*L_ + i0 + tid*4);
    CP_COMMIT;
    ld_kv(0, 0); CP_COMMIT;
    CP_WAIT1;
    __syncthreads();

    unsigned qf[2][2][4];
    float tiv[2][2];
#pragma unroll
    for (int mt = 0; mt < 2; mt++) {
      int r = warp*32 + mt*16;
#pragma unroll
      for (int kk = 0; kk < 2; kk++)
        ldm4(qf[mt][kk], sbase + (((r + l15)*36 + kk*8 + lhi) << 2));
      tiv[mt][0] = tq[r + gr];
      tiv[mt][1] = tq[r + gr + 8];
    }
    __syncwarp();

    float lrow[2][2] = {};
    float oacc[2][4][4] = {};

    for (int jt = 0; jt < njt; jt++) {
      int cur = jt & 1;
      if (jt + 1 < njt) { ld_kv(cur^1, (jt+1)*64); CP_COMMIT; CP_WAIT1; }
      else CP_WAIT0;
      __syncthreads();
      unsigned kbase = 4608 + cur*1280;
      unsigned vbase = 7168 + cur*1280;
      const float* tsf = (const float*)(smem + 9856 + cur*64);
      const unsigned char* msf = (const unsigned char*)(smem + 9984 + cur*16);

#pragma unroll
      for (int mt = 0; mt < 2; mt++) {
        float sA[8][4] = {};
#pragma unroll
        for (int kk = 0; kk < 2; kk++) {
          unsigned coff = kk*8 + lhi;
#pragma unroll
          for (int p2 = 0; p2 < 4; p2++) {
            unsigned t[4];
            ldm4(t, sbase + ((kbase + (p2*16 + l15)*20 + coff) << 2));
            unsigned b0[2] = { t[0], t[2] };
            unsigned b1[2] = { t[1], t[3] };
            mma_f16(sA[2*p2],   qf[mt][kk], b0, sA[2*p2]);
            mma_f16(sA[2*p2+1], qf[mt][kk], b1, sA[2*p2+1]);
          }
        }
        float ti0 = tiv[mt][0], ti1 = tiv[mt][1];
        int pr = warp*32 + mt*16 + gr;
        float rs0 = 0.f, rs1 = 0.f;
#pragma unroll
        for (int nt = 0; nt < 8; nt++) {
          int jc = nt*8 + 2*q;
          float tj0 = tsf[jc], tj1 = tsf[jc+1];
          bool m0 = msf[jc], m1 = msf[jc+1];
          float l00 = lg2f(1.f + fabsf(ti0 - tj0));
          float l01 = lg2f(1.f + fabsf(ti0 - tj1));
          float l10 = lg2f(1.f + fabsf(ti1 - tj0));
          float l11 = lg2f(1.f + fabsf(ti1 - tj1));
          float p0 = m0 ? 0.f : ex2f(fmaf(sA[nt][0], scaleL, fmaf(tw, l00, tbL)));
          float p1 = m1 ? 0.f : ex2f(fmaf(sA[nt][1], scaleL, fmaf(tw, l01, tbL)));
          float p2 = m0 ? 0.f : ex2f(fmaf(sA[nt][2], scaleL, fmaf(tw, l10, tbL)));
          float p3 = m1 ? 0.f : ex2f(fmaf(sA[nt][3], scaleL, fmaf(tw, l11, tbL)));
          rs0 += p0 + p1; rs1 += p2 + p3;
          Pb[pr*36 + nt*4 + q]     = h2u(__floats2half2_rn(p0, p1));
          Pb[(pr+8)*36 + nt*4 + q] = h2u(__floats2half2_rn(p2, p3));
        }
        lrow[mt][0] += rs0;
        lrow[mt][1] += rs1;
        __syncwarp();

        int pr0 = warp*32 + mt*16;
#pragma unroll
        for (int kk2 = 0; kk2 < 4; kk2++) {
          unsigned pa[4];
          ldm4(pa, sbase + (((pr0 + l15)*36 + kk2*8 + lhi) << 2));
#pragma unroll
          for (int p2 = 0; p2 < 2; p2++) {
            unsigned t[4];
            ldm4t(t, sbase + ((vbase + (kk2*16 + l15)*20 + p2*8 + lhi) << 2));
            unsigned v0[2] = { t[0], t[1] };
            unsigned v1[2] = { t[2], t[3] };
            mma_f16(oacc[mt][2*p2],   pa, v0, oacc[mt][2*p2]);
            mma_f16(oacc[mt][2*p2+1], pa, v1, oacc[mt][2*p2+1]);
          }
        }
      }
      __syncthreads();
    }

#pragma unroll
    for (int mt = 0; mt < 2; mt++) {
      float s0 = lrow[mt][0], s1 = lrow[mt][1];
      s0 += __shfl_xor_sync(~0u, s0, 1); s0 += __shfl_xor_sync(~0u, s0, 2);
      s1 += __shfl_xor_sync(~0u, s1, 1); s1 += __shfl_xor_sync(~0u, s1, 2);
      float inv0 = 1.f / s0, inv1 = 1.f / s1;
      int rr = i0 + warp*32 + mt*16 + gr;
#pragma unroll
      for (int nt = 0; nt < 4; nt++) {
        int c = h*DH_ + nt*8 + 2*q;
        *(half2*)(g_o + (long)(b*L_ + rr)*D_ + c) =
            __floats2half2_rn(oacc[mt][nt][0]*inv0, oacc[mt][nt][1]*inv0);
        *(half2*)(g_o + (long)(b*L_ + rr + 8)*D_ + c) =
            __floats2half2_rn(oacc[mt][nt][2]*inv1, oacc[mt][nt][3]*inv1);
      }
    }
  }
}

// ---------------- final head ----------------
__global__ __launch_bounds__(256) void head_kernel(
    const float* __restrict__ w1, const float* __restrict__ b1,
    const float* __restrict__ w2, const float* __restrict__ b2,
    float* __restrict__ out, int out_size) {
  int b = blockIdx.x, tid = threadIdx.x;
  int idx = g_len[b] - 1;
  __shared__ float ls[D_];
  float xv = g_x[(long)(b*L_+idx)*D_ + tid];
  ls[tid] = xv;
  if (16 + b*D_ + tid < out_size)
    out[16 + b*D_ + tid] = xv;
  __syncthreads();
  __shared__ float hh[128];
  if (tid < 128) {
    float s = b1[tid];
    const float4* wp = (const float4*)(w1 + tid*D_);
#pragma unroll 8
    for (int k4 = 0; k4 < D_/4; k4++) {
      float4 w = wp[k4];
      s += ls[k4*4+0]*w.x + ls[k4*4+1]*w.y + ls[k4*4+2]*w.z + ls[k4*4+3]*w.w;
    }
    hh[tid] = fmaxf(s, 0.f);
  }
  __syncthreads();
  if (tid < 32) {
    float s = 0.f;
    for (int j = tid; j < 128; j += 32) s += hh[j]*w2[j];
#pragma unroll
    for (int off = 16; off; off >>= 1) s += __shfl_xor_sync(~0u, s, off);
    if (tid == 0) out[b] = s + b2[0];
  }
}

// ---------------- host ----------------
extern "C" void kernel_launch(void* const* d_in, const int* in_sizes, int n_in,
                              void* d_out, int out_size) {
  const float* feat  = (const float*)d_in[0];
  const void*  maskraw = d_in[1];
  const float* pe    = (const float*)d_in[2];
  const float* in_w  = (const float*)d_in[3];
  const float* in_b  = (const float*)d_in[4];
  const float* time_w= (const float*)d_in[5];
  const float* time_b= (const float*)d_in[6];
  const float* qkv_w = (const float*)d_in[7];
  const float* qkv_b = (const float*)d_in[8];
  const float* out_w = (const float*)d_in[9];
  const float* out_b = (const float*)d_in[10];
  const float* ln1_g = (const float*)d_in[11];
  const float* ln1_b = (const float*)d_in[12];
  const float* ff1_w = (const float*)d_in[13];
  const float* ff1_b = (const float*)d_in[14];
  const float* ff2_w = (const float*)d_in[15];
  const float* ff2_b = (const float*)d_in[16];
  const float* ln2_g = (const float*)d_in[17];
  const float* ln2_b = (const float*)d_in[18];
  const float* reg1_w= (const float*)d_in[19];
  const float* reg1_b= (const float*)d_in[20];
  const float* reg2_w= (const float*)d_in[21];
  const float* reg2_b= (const float*)d_in[22];
  float* out = (float*)d_out;

  float *px;
  __half *pxr, *pqkvh, *poh, *phh, *pwh, *pfr;
  cudaGetSymbolAddress((void**)&px,   g_x);
  cudaGetSymbolAddress((void**)&pxr,  g_xr);
  cudaGetSymbolAddress((void**)&pqkvh,g_qkvh);
  cudaGetSymbolAddress((void**)&poh,  g_o);
  cudaGetSymbolAddress((void**)&phh,  g_h);
  cudaGetSymbolAddress((void**)&pwh,  g_wh);
  cudaGetSymbolAddress((void**)&pfr,  g_fr);

  static int smem_set = 0;
  if (!smem_set) {
    cudaFuncSetAttribute(attn_mma, cudaFuncAttributeMaxDynamicSharedMemorySize, ATT_SMEM);
    cudaFuncSetAttribute(gemm_ln,  cudaFuncAttributeMaxDynamicSharedMemorySize, GLN_SMEM);
    cudaFuncSetAttribute(gemm_tc<2,false,true>,  cudaFuncAttributeMaxDynamicSharedMemorySize, GEMM_SMEM);
    cudaFuncSetAttribute(gemm_tc<1,false,false>, cudaFuncAttributeMaxDynamicSharedMemorySize, GEMM_SMEM);
    cudaFuncSetAttribute(gemm_tc<1,true,false>,  cudaFuncAttributeMaxDynamicSharedMemorySize, GEMM_SMEM);
    smem_set = 1;
  }

  prep_kernel<<<B_, 1024>>>((const unsigned int*)maskraw, feat);
  wconv_kernel<<<1024, 256>>>(feat, in_w, qkv_w, out_w, ff1_w, ff2_w);
  // embed: half feat @ half in_w -> exact g_x + half g_xr, +pe
  gemm_tc<2,false,true><<<dim3(D_/64, BL_/128), 256, GEMM_SMEM>>>(
      pfr, pwh + OFF_INW, in_b, px, pxr, pe, D_, IN_);

  for (int layer = 0; layer < NL_; layer++) {
    gemm_tc<1,false,false><<<dim3(3*D_/64, BL_/128), 256, GEMM_SMEM>>>(
        pxr, pwh + OFF_QKVW + layer*3*D_*D_, qkv_b + layer*3*D_,
        nullptr, pqkvh, nullptr, 3*D_, D_);
    attn_mma<<<444, 128, ATT_SMEM>>>(time_w, time_b);
    // out-proj fused with residual + LN1
    gemm_ln<<<BL_/64, 256, GLN_SMEM>>>(
        poh, pwh + OFF_OUTW + layer*D_*D_, out_b + layer*D_,
        ln1_g + layer*D_, ln1_b + layer*D_, D_);
    gemm_tc<1,true,false><<<dim3(DFF_/64, BL_/128), 256, GEMM_SMEM>>>(
        pxr, pwh + OFF_FF1W + layer*DFF_*D_, ff1_b + layer*DFF_,
        nullptr, phh, nullptr, DFF_, D_);
    // FF2 fused with residual + LN2
    gemm_ln<<<BL_/64, 256, GLN_SMEM>>>(
        phh, pwh + OFF_FF2W + layer*D_*DFF_, ff2_b + layer*D_,
        ln2_g + layer*D_, ln2_b + layer*D_, DFF_);
  }

  head_kernel<<<B_, 256>>>(reg1_w, reg1_b, reg2_w, reg2_b, out, out_size);
}

// round 17
// speedup vs baseline: 1.0457x; 1.0457x over previous
#include <cuda_runtime.h>
#include <cuda_fp16.h>
#include <math.h>

#define B_   16
#define L_   1024
#define IN_  32
#define D_   256
#define H_   8
#define NL_  2
#define DFF_ 1024
#define DH_  32
#define BL_  (B_*L_)

// ---------------- half-operand weight layout ----------------
#define OFF_INW  0
#define SZ_INW   (D_*IN_)
#define OFF_QKVW (OFF_INW+SZ_INW)
#define SZ_QKVW  (NL_*3*D_*D_)
#define OFF_OUTW (OFF_QKVW+SZ_QKVW)
#define SZ_OUTW  (NL_*D_*D_)
#define OFF_FF1W (OFF_OUTW+SZ_OUTW)
#define SZ_FF1W  (NL_*DFF_*D_)
#define OFF_FF2W (OFF_FF1W+SZ_FF1W)
#define SZ_FF2W  (NL_*D_*DFF_)
#define WR_TOTAL (OFF_FF2W+SZ_FF2W)

// ---------------- scratch (device globals; zero-initialized) ----------------
__device__ float g_x[BL_*D_];         // exact activations (residual / outputs)
__device__ __half g_xr[BL_*D_];       // half copy (MMA A operand)
__device__ __half g_qkvh[BL_*3*D_];   // Q|K|V half [BL][768]
__device__ __half g_o[BL_*D_];        // attention out (half)
__device__ float g_p[BL_*D_];         // exact residual
__device__ __half g_h[BL_*DFF_];      // ff hidden half
__device__ float g_t[BL_];
__device__ unsigned char g_mask[BL_];
__device__ int g_len[B_];
__device__ __half g_wh[WR_TOTAL];     // half weights
__device__ __half g_fr[BL_*IN_];      // half features

// ---------------- helpers ----------------
__device__ __forceinline__ void mma_f16(float* d, const unsigned* a,
                                        const unsigned* b, const float* c) {
  asm volatile(
    "mma.sync.aligned.m16n8k16.row.col.f32.f16.f16.f32 "
    "{%0,%1,%2,%3},{%4,%5,%6,%7},{%8,%9},{%10,%11,%12,%13};"
    : "=f"(d[0]),"=f"(d[1]),"=f"(d[2]),"=f"(d[3])
    : "r"(a[0]),"r"(a[1]),"r"(a[2]),"r"(a[3]),
      "r"(b[0]),"r"(b[1]),
      "f"(c[0]),"f"(c[1]),"f"(c[2]),"f"(c[3]));
}
__device__ __forceinline__ void ldm4(unsigned* r, unsigned saddr) {
  asm volatile("ldmatrix.sync.aligned.m8n8.x4.shared.b16 {%0,%1,%2,%3}, [%4];"
    : "=r"(r[0]),"=r"(r[1]),"=r"(r[2]),"=r"(r[3]) : "r"(saddr));
}
__device__ __forceinline__ void ldm4t(unsigned* r, unsigned saddr) {
  asm volatile("ldmatrix.sync.aligned.m8n8.x4.trans.shared.b16 {%0,%1,%2,%3}, [%4];"
    : "=r"(r[0]),"=r"(r[1]),"=r"(r[2]),"=r"(r[3]) : "r"(saddr));
}
__device__ __forceinline__ void cp16(unsigned* smem_ptr, const void* gptr) {
  unsigned s = (unsigned)__cvta_generic_to_shared(smem_ptr);
  asm volatile("cp.async.ca.shared.global [%0], [%1], 16;" :: "r"(s), "l"(gptr));
}
#define CP_COMMIT asm volatile("cp.async.commit_group;")
#define CP_WAIT1  asm volatile("cp.async.wait_group 1;")
#define CP_WAIT0  asm volatile("cp.async.wait_group 0;")
__device__ __forceinline__ float lg2f(float x) {
  float r; asm("lg2.approx.f32 %0, %1;" : "=f"(r) : "f"(x)); return r;
}
__device__ __forceinline__ float ex2f(float x) {
  float r; asm("ex2.approx.f32 %0, %1;" : "=f"(r) : "f"(x)); return r;
}
__device__ __forceinline__ unsigned h2u(half2 h) {
  return *reinterpret_cast<unsigned*>(&h);
}

// ---------------- weight/feature conversion to half ----------------
__global__ __launch_bounds__(256) void wconv_kernel(
    const float* __restrict__ feat, const float* __restrict__ in_w,
    const float* __restrict__ qkv_w, const float* __restrict__ out_w,
    const float* __restrict__ ff1_w, const float* __restrict__ ff2_w) {
  int g = blockIdx.x*blockDim.x + threadIdx.x;
  int stride = gridDim.x*blockDim.x;
  for (int i = g; i < BL_*IN_; i += stride) g_fr[i] = __float2half_rn(feat[i]);
  for (int i = g; i < SZ_INW;  i += stride) g_wh[OFF_INW+i]  = __float2half_rn(in_w[i]);
  for (int i = g; i < SZ_QKVW; i += stride) g_wh[OFF_QKVW+i] = __float2half_rn(qkv_w[i]);
  for (int i = g; i < SZ_OUTW; i += stride) g_wh[OFF_OUTW+i] = __float2half_rn(out_w[i]);
  for (int i = g; i < SZ_FF1W; i += stride) g_wh[OFF_FF1W+i] = __float2half_rn(ff1_w[i]);
  for (int i = g; i < SZ_FF2W; i += stride) g_wh[OFF_FF2W+i] = __float2half_rn(ff2_w[i]);
}

// ---------------- fused prep ----------------
__global__ __launch_bounds__(1024) void prep_kernel(
    const unsigned int* __restrict__ mraw, const float* __restrict__ feat) {
  __shared__ int bad;
  __shared__ int slen;
  __shared__ float wsum[32];
  int b = blockIdx.x, tid = threadIdx.x;
  int lane = tid & 31, warp = tid >> 5;
  if (tid == 0) { bad = 0; slen = 0; }
  __syncthreads();
  for (int k = tid; k < 4096; k += 1024) {
    unsigned v = mraw[k];
    if (v != 0u && v != 1u && v != 0x3F800000u) atomicOr(&bad, 1);
  }
  __syncthreads();
  int mode4 = !bad;
  int j = b*L_ + tid;
  unsigned char m = mode4 ? (mraw[j] != 0u)
                          : (((const unsigned char*)mraw)[j] != 0);
  g_mask[j] = m;
  if (!m) atomicAdd(&slen, 1);
  float v = feat[(long)j*IN_ + (IN_-2)];
#pragma unroll
  for (int off = 1; off < 32; off <<= 1) {
    float n = __shfl_up_sync(~0u, v, off);
    if (lane >= off) v += n;
  }
  if (lane == 31) wsum[warp] = v;
  __syncthreads();
  if (warp == 0) {
    float w = wsum[lane];
#pragma unroll
    for (int off = 1; off < 32; off <<= 1) {
      float n = __shfl_up_sync(~0u, w, off);
      if (lane >= off) w += n;
    }
    wsum[lane] = w;
  }
  __syncthreads();
  float base = warp ? wsum[warp-1] : 0.f;
  g_t[j] = v + base;
  if (tid == 0) g_len[b] = slen;
}

// ---------------- FP16 GEMM (2-stage, ldmatrix) ----------------
#define GEMM_SMEM (7680*4)
template<int WMODE, bool RELU, bool PE>
__global__ __launch_bounds__(256, 3) void gemm_tc(
    const __half* __restrict__ A, const __half* __restrict__ W,
    const float* __restrict__ bias, float* __restrict__ Cf,
    __half* __restrict__ Ch, const float* __restrict__ pe, int N, int K) {
  int m_blk = blockIdx.y * 128, n_blk = blockIdx.x * 64;
  if ((m_blk & (L_-1)) >= g_len[m_blk >> 10]) return;
  extern __shared__ unsigned gsm[];
  unsigned sbase = (unsigned)__cvta_generic_to_shared(gsm);
  int tid = threadIdx.x, lane = tid & 31, warp = tid >> 5;
  int wm = warp >> 1, wn = warp & 1;
  int gr = lane >> 2, q = lane & 3;
  int l15 = lane & 15, lhi = (lane >> 4) << 2;
  float acc[2][4][4] = {};

  auto ld_stage = [&](int s, int k0) {
    unsigned* As = gsm + s*2560;
#pragma unroll
    for (int p = 0; p < 2; p++) {
      int id = p*256 + tid, row = id >> 2, c4 = id & 3;
      cp16(As + row*20 + c4*4, A + (long)(m_blk + row)*K + k0 + c4*8);
    }
    unsigned* Bs = gsm + 5120 + s*1280;
    {
      int row = tid >> 2, c4 = tid & 3;
      cp16(Bs + row*20 + c4*4, W + (long)(n_blk + row)*K + k0 + c4*8);
    }
  };

  ld_stage(0, 0); CP_COMMIT;
  int st = 0;
  for (int k0 = 0; k0 < K; k0 += 32) {
    if (k0 + 32 < K) { ld_stage(st^1, k0+32); CP_COMMIT; CP_WAIT1; }
    else CP_WAIT0;
    __syncthreads();
#pragma unroll
    for (int kk = 0; kk < 2; kk++) {
      unsigned coff = kk*8 + lhi;
      unsigned afr[2][4];
#pragma unroll
      for (int mt = 0; mt < 2; mt++)
        ldm4(afr[mt], sbase + ((st*2560 + (wm*32 + mt*16 + l15)*20 + coff) << 2));
      unsigned bfr[4][2];
#pragma unroll
      for (int p2 = 0; p2 < 2; p2++) {
        unsigned t[4];
        ldm4(t, sbase + ((5120 + st*1280 + (wn*32 + p2*16 + l15)*20 + coff) << 2));
        bfr[p2*2][0]=t[0];   bfr[p2*2][1]=t[2];
        bfr[p2*2+1][0]=t[1]; bfr[p2*2+1][1]=t[3];
      }
#pragma unroll
      for (int mt = 0; mt < 2; mt++)
#pragma unroll
        for (int nt = 0; nt < 4; nt++)
          mma_f16(acc[mt][nt], afr[mt], bfr[nt], acc[mt][nt]);
    }
    __syncthreads();
    st ^= 1;
  }
#pragma unroll
  for (int mt = 0; mt < 2; mt++) {
    int r0 = m_blk + wm*32 + mt*16 + gr;
#pragma unroll
    for (int nt = 0; nt < 4; nt++) {
      int c0 = n_blk + wn*32 + nt*8 + 2*q;
      float b0v = bias[c0], b1v = bias[c0+1];
      float v0 = acc[mt][nt][0] + b0v, v1 = acc[mt][nt][1] + b1v;
      float v2 = acc[mt][nt][2] + b0v, v3 = acc[mt][nt][3] + b1v;
      if (PE) {
        v0 += pe[(long)(r0 & (L_-1))*D_ + c0];
        v1 += pe[(long)(r0 & (L_-1))*D_ + c0 + 1];
        v2 += pe[(long)((r0+8) & (L_-1))*D_ + c0];
        v3 += pe[(long)((r0+8) & (L_-1))*D_ + c0 + 1];
      }
      if (RELU) { v0=fmaxf(v0,0.f); v1=fmaxf(v1,0.f); v2=fmaxf(v2,0.f); v3=fmaxf(v3,0.f); }
      if (WMODE == 0 || WMODE == 2) {
        *(float2*)(Cf + (long)r0*N + c0)     = make_float2(v0, v1);
        *(float2*)(Cf + (long)(r0+8)*N + c0) = make_float2(v2, v3);
      }
      if (WMODE == 1 || WMODE == 2) {
        *(half2*)(Ch + (long)r0*N + c0)     = __floats2half2_rn(v0, v1);
        *(half2*)(Ch + (long)(r0+8)*N + c0) = __floats2half2_rn(v2, v3);
      }
    }
  }
}

// ---------------- flash attention: register-P direct PV feed --------------
// P fragments never touch smem: the epilogue's (gr, nt*8+2q) value layout IS
// the m16n8k16 A-fragment layout for the PV mma. Pb holds Q only.
// smem words: Pb[128][36] @0, K 2x(64*20) @4608, V 2x(64*20) @7168,
//   tq[128] @9728, ts 2x64 @9856, ms 2x16w @9984.  total 10016 w.
#define ATT_SMEM (10016*4)
#define N_WORK   (B_*H_*(L_/128))
__global__ __launch_bounds__(128, 3) void attn_mma(
    const float* __restrict__ tw_p, const float* __restrict__ tb_p) {
  extern __shared__ unsigned smem[];
  unsigned* Pb = smem;
  unsigned sbase = (unsigned)__cvta_generic_to_shared(smem);
  float* tq = (float*)(smem + 9728);

  int tid = threadIdx.x, lane = tid & 31, warp = tid >> 5;
  int gr = lane >> 2, q = lane & 3;
  int l15 = lane & 15, lhi = (lane >> 4) << 2;

  const float LOG2E = 1.4426950408889634f;
  float tw = -fabsf(tw_p[0]);
  float tbL = tb_p[0] * LOG2E;
  const float scaleL = 0.17677669529663687f * LOG2E;

  for (int w = blockIdx.x; w < N_WORK; w += gridDim.x) {
    int iblk = w & 7, bh = w >> 3;
    int b = bh >> 3, h = bh & 7;
    int i0 = iblk * 128;
    int len = g_len[b];
    if (i0 >= len) continue;
    int njt = (len + 63) >> 6;

    auto ld_kv = [&](int s, int j0) {
      unsigned* Kb = smem + 4608 + s*1280;
      unsigned* Vb = smem + 7168 + s*1280;
#pragma unroll
      for (int p = 0; p < 2; p++) {
        int id = p*128 + tid, row = id >> 2, c4 = id & 3;
        long base = (long)(b*L_ + j0 + row)*768 + h*DH_ + c4*8;
        cp16(Kb + row*20 + c4*4, g_qkvh + base + 256);
        cp16(Vb + row*20 + c4*4, g_qkvh + base + 512);
      }
      if (tid < 16)      cp16(smem + 9856 + s*64 + tid*4, g_t + b*L_ + j0 + tid*4);
      else if (tid < 20) cp16(smem + 9984 + s*16 + (tid-16)*4,
                              g_mask + b*L_ + j0 + (tid-16)*16);
    };

    // Q (half) + query times
#pragma unroll
    for (int p = 0; p < 4; p++) {
      int id = p*128 + tid, row = id >> 2, c4 = id & 3;
      cp16(Pb + row*36 + c4*4,
           g_qkvh + (long)(b*L_ + i0 + row)*768 + h*DH_ + c4*8);
    }
    if (tid < 32) cp16((unsigned*)tq + tid*4, g_t + b*L_ + i0 + tid*4);
    CP_COMMIT;
    ld_kv(0, 0); CP_COMMIT;
    CP_WAIT1;
    __syncthreads();

    unsigned qf[2][2][4];
    float tiv[2][2];
#pragma unroll
    for (int mt = 0; mt < 2; mt++) {
      int r = warp*32 + mt*16;
#pragma unroll
      for (int kk = 0; kk < 2; kk++)
        ldm4(qf[mt][kk], sbase + (((r + l15)*36 + kk*8 + lhi) << 2));
      tiv[mt][0] = tq[r + gr];
      tiv[mt][1] = tq[r + gr + 8];
    }
    __syncwarp();

    float lrow[2][2] = {};
    float oacc[2][4][4] = {};

    for (int jt = 0; jt < njt; jt++) {
      int cur = jt & 1;
      if (jt + 1 < njt) { ld_kv(cur^1, (jt+1)*64); CP_COMMIT; CP_WAIT1; }
      else CP_WAIT0;
      __syncthreads();
      unsigned kbase = 4608 + cur*1280;
      unsigned vbase = 7168 + cur*1280;
      const float* tsf = (const float*)(smem + 9856 + cur*64);
      const unsigned char* msf = (const unsigned char*)(smem + 9984 + cur*16);

#pragma unroll
      for (int mt = 0; mt < 2; mt++) {
        // ---- S = Q K^T ----
        float sA[8][4] = {};
#pragma unroll
        for (int kk = 0; kk < 2; kk++) {
          unsigned coff = kk*8 + lhi;
#pragma unroll
          for (int p2 = 0; p2 < 4; p2++) {
            unsigned t[4];
            ldm4(t, sbase + ((kbase + (p2*16 + l15)*20 + coff) << 2));
            unsigned b0[2] = { t[0], t[2] };
            unsigned b1[2] = { t[1], t[3] };
            mma_f16(sA[2*p2],   qf[mt][kk], b0, sA[2*p2]);
            mma_f16(sA[2*p2+1], qf[mt][kk], b1, sA[2*p2+1]);
          }
        }
        // ---- epilogue: bias + exp; P stays in registers (A-frag layout) ----
        float ti0 = tiv[mt][0], ti1 = tiv[mt][1];
        unsigned ph[8][2];          // ph[nt][0]: rows gr; ph[nt][1]: rows gr+8
        float rs0 = 0.f, rs1 = 0.f;
#pragma unroll
        for (int nt = 0; nt < 8; nt++) {
          int jc = nt*8 + 2*q;
          float tj0 = tsf[jc], tj1 = tsf[jc+1];
          bool m0 = msf[jc], m1 = msf[jc+1];
          float l00 = lg2f(1.f + fabsf(ti0 - tj0));
          float l01 = lg2f(1.f + fabsf(ti0 - tj1));
          float l10 = lg2f(1.f + fabsf(ti1 - tj0));
          float l11 = lg2f(1.f + fabsf(ti1 - tj1));
          float p0 = m0 ? 0.f : ex2f(fmaf(sA[nt][0], scaleL, fmaf(tw, l00, tbL)));
          float p1 = m1 ? 0.f : ex2f(fmaf(sA[nt][1], scaleL, fmaf(tw, l01, tbL)));
          float p2 = m0 ? 0.f : ex2f(fmaf(sA[nt][2], scaleL, fmaf(tw, l10, tbL)));
          float p3 = m1 ? 0.f : ex2f(fmaf(sA[nt][3], scaleL, fmaf(tw, l11, tbL)));
          rs0 += p0 + p1; rs1 += p2 + p3;
          ph[nt][0] = h2u(__floats2half2_rn(p0, p1));
          ph[nt][1] = h2u(__floats2half2_rn(p2, p3));
        }
        lrow[mt][0] += rs0;
        lrow[mt][1] += rs1;

        // ---- O += P V (P direct from registers) ----
#pragma unroll
        for (int kk2 = 0; kk2 < 4; kk2++) {
          unsigned pa[4] = { ph[2*kk2][0],   ph[2*kk2][1],
                             ph[2*kk2+1][0], ph[2*kk2+1][1] };
#pragma unroll
          for (int p2 = 0; p2 < 2; p2++) {
            unsigned t[4];
            ldm4t(t, sbase + ((vbase + (kk2*16 + l15)*20 + p2*8 + lhi) << 2));
            unsigned v0[2] = { t[0], t[1] };
            unsigned v1[2] = { t[2], t[3] };
            mma_f16(oacc[mt][2*p2],   pa, v0, oacc[mt][2*p2]);
            mma_f16(oacc[mt][2*p2+1], pa, v1, oacc[mt][2*p2+1]);
          }
        }
      }
      __syncthreads();
    }

#pragma unroll
    for (int mt = 0; mt < 2; mt++) {
      float s0 = lrow[mt][0], s1 = lrow[mt][1];
      s0 += __shfl_xor_sync(~0u, s0, 1); s0 += __shfl_xor_sync(~0u, s0, 2);
      s1 += __shfl_xor_sync(~0u, s1, 1); s1 += __shfl_xor_sync(~0u, s1, 2);
      float inv0 = 1.f / s0, inv1 = 1.f / s1;
      int rr = i0 + warp*32 + mt*16 + gr;
#pragma unroll
      for (int nt = 0; nt < 4; nt++) {
        int c = h*DH_ + nt*8 + 2*q;
        *(half2*)(g_o + (long)(b*L_ + rr)*D_ + c) =
            __floats2half2_rn(oacc[mt][nt][0]*inv0, oacc[mt][nt][1]*inv0);
        *(half2*)(g_o + (long)(b*L_ + rr + 8)*D_ + c) =
            __floats2half2_rn(oacc[mt][nt][2]*inv1, oacc[mt][nt][3]*inv1);
      }
    }
  }
}

// ---------------- x = LN(x + r) * g + b : exact fp32 + half copies --------
__global__ __launch_bounds__(256) void add_ln_kernel(
    float* __restrict__ x, const float* __restrict__ r,
    const float* __restrict__ g, const float* __restrict__ bt) {
  int row0 = blockIdx.x * 4;
  if ((row0 & (L_-1)) >= g_len[row0 >> 10]) return;
  int tid = threadIdx.x;
  int sub = tid >> 6, t = tid & 63;
  int row = row0 + sub;
  int lane = tid & 31, warp = tid >> 5;
  bool valid = (row & (L_-1)) < g_len[row >> 10];
  __shared__ float red[8];

  float4 xv = *(const float4*)(x + (long)row*D_ + t*4);
  float4 rv = *(const float4*)(r + (long)row*D_ + t*4);
  float4 v = make_float4(xv.x+rv.x, xv.y+rv.y, xv.z+rv.z, xv.w+rv.w);
  float s = v.x + v.y + v.z + v.w;
#pragma unroll
  for (int off = 16; off; off >>= 1) s += __shfl_xor_sync(~0u, s, off);
  if (lane == 0) red[warp] = s;
  __syncthreads();
  float mean = (red[sub*2] + red[sub*2+1]) * (1.f/D_);
  float4 c = make_float4(v.x-mean, v.y-mean, v.z-mean, v.w-mean);
  float s2 = c.x*c.x + c.y*c.y + c.z*c.z + c.w*c.w;
  __syncthreads();
#pragma unroll
  for (int off = 16; off; off >>= 1) s2 += __shfl_xor_sync(~0u, s2, off);
  if (lane == 0) red[warp] = s2;
  __syncthreads();
  float rstd = rsqrtf((red[sub*2] + red[sub*2+1]) * (1.f/D_) + 1e-5f);
  float4 gv = *(const float4*)(g + t*4);
  float4 bv = *(const float4*)(bt + t*4);
  if (valid) {
    float o0 = c.x*rstd*gv.x + bv.x, o1 = c.y*rstd*gv.y + bv.y;
    float o2 = c.z*rstd*gv.z + bv.z, o3 = c.w*rstd*gv.w + bv.w;
    *(float4*)(x + (long)row*D_ + t*4) = make_float4(o0, o1, o2, o3);
    half2* xr2 = (half2*)(g_xr + (long)row*D_ + t*4);
    xr2[0] = __floats2half2_rn(o0, o1);
    xr2[1] = __floats2half2_rn(o2, o3);
  }
}

// ---------------- final head ----------------
__global__ __launch_bounds__(256) void head_kernel(
    const float* __restrict__ w1, const float* __restrict__ b1,
    const float* __restrict__ w2, const float* __restrict__ b2,
    float* __restrict__ out, int out_size) {
  int b = blockIdx.x, tid = threadIdx.x;
  int idx = g_len[b] - 1;
  __shared__ float ls[D_];
  float xv = g_x[(long)(b*L_+idx)*D_ + tid];
  ls[tid] = xv;
  if (16 + b*D_ + tid < out_size)
    out[16 + b*D_ + tid] = xv;
  __syncthreads();
  __shared__ float hh[128];
  if (tid < 128) {
    float s = b1[tid];
    const float4* wp = (const float4*)(w1 + tid*D_);
#pragma unroll 8
    for (int k4 = 0; k4 < D_/4; k4++) {
      float4 w = wp[k4];
      s += ls[k4*4+0]*w.x + ls[k4*4+1]*w.y + ls[k4*4+2]*w.z + ls[k4*4+3]*w.w;
    }
    hh[tid] = fmaxf(s, 0.f);
  }
  __syncthreads();
  if (tid < 32) {
    float s = 0.f;
    for (int j = tid; j < 128; j += 32) s += hh[j]*w2[j];
#pragma unroll
    for (int off = 16; off; off >>= 1) s += __shfl_xor_sync(~0u, s, off);
    if (tid == 0) out[b] = s + b2[0];
  }
}

// ---------------- host ----------------
extern "C" void kernel_launch(void* const* d_in, const int* in_sizes, int n_in,
                              void* d_out, int out_size) {
  const float* feat  = (const float*)d_in[0];
  const void*  maskraw = d_in[1];
  const float* pe    = (const float*)d_in[2];
  const float* in_w  = (const float*)d_in[3];
  const float* in_b  = (const float*)d_in[4];
  const float* time_w= (const float*)d_in[5];
  const float* time_b= (const float*)d_in[6];
  const float* qkv_w = (const float*)d_in[7];
  const float* qkv_b = (const float*)d_in[8];
  const float* out_w = (const float*)d_in[9];
  const float* out_b = (const float*)d_in[10];
  const float* ln1_g = (const float*)d_in[11];
  const float* ln1_b = (const float*)d_in[12];
  const float* ff1_w = (const float*)d_in[13];
  const float* ff1_b = (const float*)d_in[14];
  const float* ff2_w = (const float*)d_in[15];
  const float* ff2_b = (const float*)d_in[16];
  const float* ln2_g = (const float*)d_in[17];
  const float* ln2_b = (const float*)d_in[18];
  const float* reg1_w= (const float*)d_in[19];
  const float* reg1_b= (const float*)d_in[20];
  const float* reg2_w= (const float*)d_in[21];
  const float* reg2_b= (const float*)d_in[22];
  float* out = (float*)d_out;

  float *px, *pp;
  __half *pxr, *pqkvh, *poh, *phh, *pwh, *pfr;
  cudaGetSymbolAddress((void**)&px,   g_x);
  cudaGetSymbolAddress((void**)&pxr,  g_xr);
  cudaGetSymbolAddress((void**)&pqkvh,g_qkvh);
  cudaGetSymbolAddress((void**)&poh,  g_o);
  cudaGetSymbolAddress((void**)&pp,   g_p);
  cudaGetSymbolAddress((void**)&phh,  g_h);
  cudaGetSymbolAddress((void**)&pwh,  g_wh);
  cudaGetSymbolAddress((void**)&pfr,  g_fr);

  static int smem_set = 0;
  if (!smem_set) {
    cudaFuncSetAttribute(attn_mma, cudaFuncAttributeMaxDynamicSharedMemorySize, ATT_SMEM);
    cudaFuncSetAttribute(gemm_tc<2,false,true>,  cudaFuncAttributeMaxDynamicSharedMemorySize, GEMM_SMEM);
    cudaFuncSetAttribute(gemm_tc<1,false,false>, cudaFuncAttributeMaxDynamicSharedMemorySize, GEMM_SMEM);
    cudaFuncSetAttribute(gemm_tc<0,false,false>, cudaFuncAttributeMaxDynamicSharedMemorySize, GEMM_SMEM);
    cudaFuncSetAttribute(gemm_tc<1,true,false>,  cudaFuncAttributeMaxDynamicSharedMemorySize, GEMM_SMEM);
    smem_set = 1;
  }

  prep_kernel<<<B_, 1024>>>((const unsigned int*)maskraw, feat);
  wconv_kernel<<<1024, 256>>>(feat, in_w, qkv_w, out_w, ff1_w, ff2_w);
  gemm_tc<2,false,true><<<dim3(D_/64, BL_/128), 256, GEMM_SMEM>>>(
      pfr, pwh + OFF_INW, in_b, px, pxr, pe, D_, IN_);

  for (int layer = 0; layer < NL_; layer++) {
    gemm_tc<1,false,false><<<dim3(3*D_/64, BL_/128), 256, GEMM_SMEM>>>(
        pxr, pwh + OFF_QKVW + layer*3*D_*D_, qkv_b + layer*3*D_,
        nullptr, pqkvh, nullptr, 3*D_, D_);
    attn_mma<<<444, 128, ATT_SMEM>>>(time_w, time_b);
    gemm_tc<0,false,false><<<dim3(D_/64, BL_/128), 256, GEMM_SMEM>>>(
        poh, pwh + OFF_OUTW + layer*D_*D_, out_b + layer*D_,
        pp, nullptr, nullptr, D_, D_);
    add_ln_kernel<<<BL_/4, 256>>>(px, pp, ln1_g + layer*D_, ln1_b + layer*D_);
    gemm_tc<1,true,false><<<dim3(DFF_/64, BL_/128), 256, GEMM_SMEM>>>(
        pxr, pwh + OFF_FF1W + layer*DFF_*D_, ff1_b + layer*DFF_,
        nullptr, phh, nullptr, DFF_, D_);
    gemm_tc<0,false,false><<<dim3(D_/64, BL_/128), 256, GEMM_SMEM>>>(
        phh, pwh + OFF_FF2W + layer*D_*DFF_, ff2_b + layer*D_,
        pp, nullptr, nullptr, D_, DFF_);
    add_ln_kernel<<<BL_/4, 256>>>(px, pp, ln2_g + layer*D_, ln2_b + layer*D_);
  }

  head_kernel<<<B_, 256>>>(reg1_w, reg1_b, reg2_w, reg2_b, out, out_size);
}